// round 7
// baseline (speedup 1.0000x reference)
#include <cuda_runtime.h>
#include <cuda_bf16.h>
#include <cstdint>

#define NN 50000
#define DD 128
#define EE 800000
#define SCAN_BS 1024
#define NB_MAX 64

// ---------------------------------------------------------------------------
// Scratch (__device__ globals; no allocations allowed)
// ---------------------------------------------------------------------------
__device__ int   g_cnt[NN];
__device__ int   g_rowptr[NN + 1];
__device__ int   g_cursor[NN];
__device__ int2  g_erec[EE];          // {src, bitcast(dinv[src])}
__device__ float g_dinv[NN];
__device__ int   g_bsum[NB_MAX];
__device__ float g_h[(size_t)NN * DD];   // raw GEMM output h = X@W
__device__ float g_a[(size_t)NN * DD];   // layer-1 output

// ---------------------------------------------------------------------------
// Helpers
// ---------------------------------------------------------------------------
__device__ __forceinline__ uint32_t f2tf(float f) {
    uint32_t r; asm("cvt.rna.tf32.f32 %0, %1;" : "=r"(r) : "f"(f)); return r;
}

// ---------------------------------------------------------------------------
// CSR build
// ---------------------------------------------------------------------------
__global__ void k_zero(int n) {
    int i = blockIdx.x * blockDim.x + threadIdx.x;
    if (i < n) g_cnt[i] = 0;
}

__global__ void k_hist(const int* __restrict__ dst, int e) {
    int i = blockIdx.x * blockDim.x + threadIdx.x;
    int n8 = e >> 3;
    if (i < n8) {
        int4 d0 = __ldg(reinterpret_cast<const int4*>(dst) + 2 * i);
        int4 d1 = __ldg(reinterpret_cast<const int4*>(dst) + 2 * i + 1);
        atomicAdd(&g_cnt[d0.x], 1); atomicAdd(&g_cnt[d0.y], 1);
        atomicAdd(&g_cnt[d0.z], 1); atomicAdd(&g_cnt[d0.w], 1);
        atomicAdd(&g_cnt[d1.x], 1); atomicAdd(&g_cnt[d1.y], 1);
        atomicAdd(&g_cnt[d1.z], 1); atomicAdd(&g_cnt[d1.w], 1);
    } else {
        int j = n8 * 8 + (i - n8);
        if (j < e) atomicAdd(&g_cnt[dst[j]], 1);
    }
}

__global__ __launch_bounds__(SCAN_BS) void k_scanA(int n) {
    __shared__ int s[SCAN_BS];
    int i = blockIdx.x * SCAN_BS + threadIdx.x;
    s[threadIdx.x] = (i < n) ? g_cnt[i] : 0;
    __syncthreads();
    for (int off = SCAN_BS / 2; off > 0; off >>= 1) {
        if (threadIdx.x < off) s[threadIdx.x] += s[threadIdx.x + off];
        __syncthreads();
    }
    if (threadIdx.x == 0) g_bsum[blockIdx.x] = s[0];
}

// parallel 64-wide exclusive scan of block sums
__global__ void k_scanB(int nb, int n) {
    __shared__ int s[64];
    int t = threadIdx.x;
    int v = (t < nb) ? g_bsum[t] : 0;
    s[t] = v;
    __syncthreads();
    for (int off = 1; off < 64; off <<= 1) {
        int u = (t >= off) ? s[t - off] : 0;
        __syncthreads();
        s[t] += u;
        __syncthreads();
    }
    if (t < nb) g_bsum[t] = s[t] - v;
    if (t == 63) g_rowptr[n] = s[63];
}

__global__ __launch_bounds__(SCAN_BS) void k_scanC(int n) {
    __shared__ int s[SCAN_BS];
    int t = threadIdx.x;
    int i = blockIdx.x * SCAN_BS + t;
    int c = (i < n) ? g_cnt[i] : 0;
    s[t] = c;
    __syncthreads();
    for (int off = 1; off < SCAN_BS; off <<= 1) {
        int v = (t >= off) ? s[t - off] : 0;
        __syncthreads();
        s[t] += v;
        __syncthreads();
    }
    if (i < n) {
        int ex = s[t] - c + g_bsum[blockIdx.x];
        g_rowptr[i] = ex;
        g_cursor[i] = ex;
        g_dinv[i]   = rsqrtf((float)(c + 1));
    }
}

// fill edge records {src, dinv[src]} bucketed by dst
__global__ void k_fill(const int* __restrict__ src, const int* __restrict__ dst, int e) {
    int i = blockIdx.x * blockDim.x + threadIdx.x;
    int n4 = e >> 2;
    if (i < n4) {
        int4 s = __ldg(reinterpret_cast<const int4*>(src) + i);
        int4 d = __ldg(reinterpret_cast<const int4*>(dst) + i);
        float v0 = g_dinv[s.x], v1 = g_dinv[s.y], v2 = g_dinv[s.z], v3 = g_dinv[s.w];
        int p0 = atomicAdd(&g_cursor[d.x], 1);
        int p1 = atomicAdd(&g_cursor[d.y], 1);
        int p2 = atomicAdd(&g_cursor[d.z], 1);
        int p3 = atomicAdd(&g_cursor[d.w], 1);
        g_erec[p0] = make_int2(s.x, __float_as_int(v0));
        g_erec[p1] = make_int2(s.y, __float_as_int(v1));
        g_erec[p2] = make_int2(s.z, __float_as_int(v2));
        g_erec[p3] = make_int2(s.w, __float_as_int(v3));
    } else {
        int j = n4 * 4 + (i - n4);
        if (j < e) {
            int s = src[j];
            int p = atomicAdd(&g_cursor[dst[j]], 1);
            g_erec[p] = make_int2(s, __float_as_int(g_dinv[s]));
        }
    }
}

// ---------------------------------------------------------------------------
// 3xTF32 mma.sync GEMM: Y[row] = (relu?)X[row] @ W  (unchanged from R5)
// ---------------------------------------------------------------------------
#define LDA 132
#define LDB 136
#define SM_A (64 * LDA)
#define SM_B (128 * LDB)
#define SM_GEMM_BYTES ((2 * SM_A + 2 * SM_B) * 4)

__device__ __forceinline__ void mma_tf32(float* c, const uint32_t* a, const uint32_t* b) {
    asm volatile(
        "mma.sync.aligned.m16n8k8.row.col.f32.tf32.tf32.f32 "
        "{%0,%1,%2,%3}, {%4,%5,%6,%7}, {%8,%9}, {%0,%1,%2,%3};"
        : "+f"(c[0]), "+f"(c[1]), "+f"(c[2]), "+f"(c[3])
        : "r"(a[0]), "r"(a[1]), "r"(a[2]), "r"(a[3]), "r"(b[0]), "r"(b[1]));
}

template <bool RELU>
__global__ __launch_bounds__(256) void k_gemm_mma(const float* __restrict__ X,
                                                  const float* __restrict__ W,
                                                  float* __restrict__ Y, int n) {
    extern __shared__ uint32_t sm[];
    uint32_t* sAh = sm;
    uint32_t* sAl = sAh + SM_A;
    uint32_t* sBh = sAl + SM_A;
    uint32_t* sBl = sBh + SM_B;

    const int tid  = threadIdx.x;
    const int row0 = blockIdx.x * 64;

#pragma unroll
    for (int idx = tid; idx < 64 * 32; idx += 256) {
        int r  = idx >> 5;
        int c4 = idx & 31;
        int row = row0 + r;
        float4 v = make_float4(0.f, 0.f, 0.f, 0.f);
        if (row < n) v = __ldg(reinterpret_cast<const float4*>(X + (size_t)row * DD) + c4);
        if (RELU) {
            v.x = fmaxf(v.x, 0.f); v.y = fmaxf(v.y, 0.f);
            v.z = fmaxf(v.z, 0.f); v.w = fmaxf(v.w, 0.f);
        }
        uint4 h, l;
        h.x = f2tf(v.x); l.x = f2tf(v.x - __uint_as_float(h.x));
        h.y = f2tf(v.y); l.y = f2tf(v.y - __uint_as_float(h.y));
        h.z = f2tf(v.z); l.z = f2tf(v.z - __uint_as_float(h.z));
        h.w = f2tf(v.w); l.w = f2tf(v.w - __uint_as_float(h.w));
        *reinterpret_cast<uint4*>(&sAh[r * LDA + c4 * 4]) = h;
        *reinterpret_cast<uint4*>(&sAl[r * LDA + c4 * 4]) = l;
    }

#pragma unroll
    for (int idx = tid; idx < 128 * 32; idx += 256) {
        int k  = idx >> 5;
        int c4 = idx & 31;
        float4 v = __ldg(reinterpret_cast<const float4*>(W + (size_t)k * DD) + c4);
        uint4 h, l;
        h.x = f2tf(v.x); l.x = f2tf(v.x - __uint_as_float(h.x));
        h.y = f2tf(v.y); l.y = f2tf(v.y - __uint_as_float(h.y));
        h.z = f2tf(v.z); l.z = f2tf(v.z - __uint_as_float(h.z));
        h.w = f2tf(v.w); l.w = f2tf(v.w - __uint_as_float(h.w));
        *reinterpret_cast<uint4*>(&sBh[k * LDB + c4 * 4]) = h;
        *reinterpret_cast<uint4*>(&sBl[k * LDB + c4 * 4]) = l;
    }
    __syncthreads();

    const int wid  = tid >> 5;
    const int lane = tid & 31;
    const int gid  = lane >> 2;
    const int tig  = lane & 3;
    const int wm   = wid & 1;
    const int wn   = wid >> 1;

    float acc[2][4][4];
#pragma unroll
    for (int mi = 0; mi < 2; mi++)
#pragma unroll
        for (int ni = 0; ni < 4; ni++)
#pragma unroll
            for (int j = 0; j < 4; j++) acc[mi][ni][j] = 0.f;

    for (int p = 0; p < 3; p++) {
        const uint32_t* As = (p == 2) ? sAl : sAh;
        const uint32_t* Bs = (p == 1) ? sBl : sBh;
#pragma unroll
        for (int ks = 0; ks < 16; ks++) {
            const int k0 = ks * 8;
            uint32_t a[2][4];
#pragma unroll
            for (int mi = 0; mi < 2; mi++) {
                int rb = wm * 32 + mi * 16;
                a[mi][0] = As[(rb + gid) * LDA + k0 + tig];
                a[mi][1] = As[(rb + gid + 8) * LDA + k0 + tig];
                a[mi][2] = As[(rb + gid) * LDA + k0 + tig + 4];
                a[mi][3] = As[(rb + gid + 8) * LDA + k0 + tig + 4];
            }
            uint32_t b[4][2];
#pragma unroll
            for (int ni = 0; ni < 4; ni++) {
                int nb = wn * 32 + ni * 8;
                b[ni][0] = Bs[(k0 + tig) * LDB + nb + gid];
                b[ni][1] = Bs[(k0 + tig + 4) * LDB + nb + gid];
            }
#pragma unroll
            for (int mi = 0; mi < 2; mi++)
#pragma unroll
                for (int ni = 0; ni < 4; ni++)
                    mma_tf32(acc[mi][ni], a[mi], b[ni]);
        }
    }

#pragma unroll
    for (int mi = 0; mi < 2; mi++) {
        int r0 = row0 + wm * 32 + mi * 16 + gid;
#pragma unroll
        for (int ni = 0; ni < 4; ni++) {
            int col = wn * 32 + ni * 8 + tig * 2;
            if (r0 < n)
                *reinterpret_cast<float2*>(Y + (size_t)r0 * DD + col) =
                    make_float2(acc[mi][ni][0], acc[mi][ni][1]);
            if (r0 + 8 < n)
                *reinterpret_cast<float2*>(Y + (size_t)(r0 + 8) * DD + col) =
                    make_float2(acc[mi][ni][2], acc[mi][ni][3]);
        }
    }
}

// ---------------------------------------------------------------------------
// Gather: out[i] = dinv[i] * (dinv[i]*h[i] + sum_in dinv[s]*h[s]) + b
// One warp per node; lane owns one float4 chunk. Unroll 8, edge records
// carry src+dinv together (2-level dependent load chain).
// ---------------------------------------------------------------------------
__global__ __launch_bounds__(256) void k_gather(const float* __restrict__ hs,
                                                const float* __restrict__ b,
                                                float* __restrict__ out, int n) {
    int g    = blockIdx.x * blockDim.x + threadIdx.x;
    int node = g >> 5;
    int lane = g & 31;
    if (node >= n) return;

    const float4* H = reinterpret_cast<const float4*>(hs);
    int beg = g_rowptr[node];
    int end = g_rowptr[node + 1];

    float dn = g_dinv[node];
    float4 sv = __ldg(&H[node * 32 + lane]);
    float4 acc = make_float4(sv.x * dn, sv.y * dn, sv.z * dn, sv.w * dn);

    int e = beg;
    for (; e + 8 <= end; e += 8) {
        int2 r[8];
#pragma unroll
        for (int j = 0; j < 8; j++) r[j] = __ldg(&g_erec[e + j]);
        float4 v[8];
#pragma unroll
        for (int j = 0; j < 8; j++) v[j] = __ldg(&H[(size_t)r[j].x * 32 + lane]);
#pragma unroll
        for (int j = 0; j < 8; j++) {
            float d = __int_as_float(r[j].y);
            acc.x = fmaf(v[j].x, d, acc.x);
            acc.y = fmaf(v[j].y, d, acc.y);
            acc.z = fmaf(v[j].z, d, acc.z);
            acc.w = fmaf(v[j].w, d, acc.w);
        }
    }
    for (; e < end; e++) {
        int2 r = __ldg(&g_erec[e]);
        float d = __int_as_float(r.y);
        float4 v = __ldg(&H[(size_t)r.x * 32 + lane]);
        acc.x = fmaf(v.x, d, acc.x);
        acc.y = fmaf(v.y, d, acc.y);
        acc.z = fmaf(v.z, d, acc.z);
        acc.w = fmaf(v.w, d, acc.w);
    }

    float4 bb = __ldg(reinterpret_cast<const float4*>(b) + lane);
    float4 o;
    o.x = fmaf(acc.x, dn, bb.x);
    o.y = fmaf(acc.y, dn, bb.y);
    o.z = fmaf(acc.z, dn, bb.z);
    o.w = fmaf(acc.w, dn, bb.w);
    reinterpret_cast<float4*>(out)[node * 32 + lane] = o;
}

// ---------------------------------------------------------------------------
// Stream/event resources
// ---------------------------------------------------------------------------
static cudaStream_t g_s1 = nullptr;
static cudaEvent_t  g_evf = nullptr, g_evj = nullptr;
namespace {
struct StreamInit {
    StreamInit() {
        if (cudaStreamCreateWithFlags(&g_s1, cudaStreamNonBlocking) != cudaSuccess) g_s1 = nullptr;
        if (cudaEventCreateWithFlags(&g_evf, cudaEventDisableTiming) != cudaSuccess) g_evf = nullptr;
        if (cudaEventCreateWithFlags(&g_evj, cudaEventDisableTiming) != cudaSuccess) g_evj = nullptr;
        cudaGetLastError();
    }
} g_stream_init;
}

// ---------------------------------------------------------------------------
// Launch
// ---------------------------------------------------------------------------
extern "C" void kernel_launch(void* const* d_in, const int* in_sizes, int n_in,
                              void* d_out, int out_size) {
    const float* x  = (const float*)d_in[0];
    const int*   ei = (const int*)d_in[1];
    const float* W1 = (const float*)d_in[2];
    const float* b1 = (const float*)d_in[3];
    const float* W2 = (const float*)d_in[4];
    const float* b2 = (const float*)d_in[5];
    float* out = (float*)d_out;

    const int n = in_sizes[0] / DD;   // 50000
    const int e = in_sizes[1] / 2;    // 800000
    const int* src = ei;
    const int* dst = ei + e;

    float *p_h = nullptr, *p_a = nullptr;
    cudaGetSymbolAddress((void**)&p_h, g_h);
    cudaGetSymbolAddress((void**)&p_a, g_a);

    cudaFuncSetAttribute(k_gemm_mma<false>, cudaFuncAttributeMaxDynamicSharedMemorySize, SM_GEMM_BYTES);
    cudaFuncSetAttribute(k_gemm_mma<true>,  cudaFuncAttributeMaxDynamicSharedMemorySize, SM_GEMM_BYTES);

    const int T = 256;
    const int nb = (n + SCAN_BS - 1) / SCAN_BS;
    const int e8threads = (e >> 3) + 8;
    const int e4threads = (e >> 2) + 4;
    const int gemm_blocks = (n + 63) / 64;
    const long long nwt = (long long)n * 32;
    const int gath_blocks = (int)((nwt + T - 1) / T);

    const bool fork = (g_s1 && g_evf && g_evj);
    cudaStream_t sc = fork ? g_s1 : (cudaStream_t)0;

    if (fork) {
        cudaEventRecord(g_evf, 0);
        cudaStreamWaitEvent(g_s1, g_evf, 0);
    }

    // CSR + normalization (side stream, overlapped with GEMM-1)
    k_zero <<<(n + T - 1) / T, T, 0, sc>>>(n);
    k_hist <<<(e8threads + T - 1) / T, T, 0, sc>>>(dst, e);
    k_scanA<<<nb, SCAN_BS, 0, sc>>>(n);
    k_scanB<<<1, 64, 0, sc>>>(nb, n);
    k_scanC<<<nb, SCAN_BS, 0, sc>>>(n);
    k_fill <<<(e4threads + T - 1) / T, T, 0, sc>>>(src, dst, e);

    // GEMM-1 on main stream (independent of CSR)
    k_gemm_mma<false><<<gemm_blocks, 256, SM_GEMM_BYTES>>>(x, W1, p_h, n);

    if (fork) {
        cudaEventRecord(g_evj, g_s1);
        cudaStreamWaitEvent(0, g_evj, 0);
    }

    // Layer 1 aggregate, Layer 2
    k_gather<<<gath_blocks, T>>>(p_h, b1, p_a, n);
    k_gemm_mma<true><<<gemm_blocks, 256, SM_GEMM_BYTES>>>(p_a, W2, p_h, n);
    k_gather<<<gath_blocks, T>>>(p_h, b2, out, n);
}

// round 8
// speedup vs baseline: 1.0343x; 1.0343x over previous
#include <cuda_runtime.h>
#include <cuda_fp16.h>
#include <cuda_bf16.h>
#include <cstdint>

#define NN 50000
#define DD 128
#define EE 800000
#define SCAN_BS 1024
#define NB_MAX 64

// ---------------------------------------------------------------------------
// Scratch (__device__ globals; no allocations allowed)
// ---------------------------------------------------------------------------
__device__ int   g_cnt[NN];
__device__ int   g_rowptr[NN + 1];
__device__ int   g_cursor[NN];
__device__ int2  g_erec[EE];               // {src, bitcast(dinv[src])}
__device__ float g_dinv[NN];
__device__ __half g_h[(size_t)NN * DD];    // GEMM output in fp16 (gather input)
__device__ float  g_a[(size_t)NN * DD];    // layer-1 output (fp32)

// decoupled-lookback scan state (reset by k_zero each call)
__device__ volatile int g_flag[NB_MAX];    // 0=invalid 1=aggregate 2=prefix
__device__ int g_aggr[NB_MAX];
__device__ int g_pref[NB_MAX];

// ---------------------------------------------------------------------------
// Helpers
// ---------------------------------------------------------------------------
__device__ __forceinline__ uint32_t f2tf(float f) {
    uint32_t r; asm("cvt.rna.tf32.f32 %0, %1;" : "=r"(r) : "f"(f)); return r;
}

// ---------------------------------------------------------------------------
// CSR build
// ---------------------------------------------------------------------------
__global__ void k_zero(int n) {
    int i = blockIdx.x * blockDim.x + threadIdx.x;
    if (i < n) g_cnt[i] = 0;
    if (i < NB_MAX) g_flag[i] = 0;
}

__global__ void k_hist(const int* __restrict__ dst, int e) {
    int i = blockIdx.x * blockDim.x + threadIdx.x;
    int n8 = e >> 3;
    if (i < n8) {
        int4 d0 = __ldg(reinterpret_cast<const int4*>(dst) + 2 * i);
        int4 d1 = __ldg(reinterpret_cast<const int4*>(dst) + 2 * i + 1);
        atomicAdd(&g_cnt[d0.x], 1); atomicAdd(&g_cnt[d0.y], 1);
        atomicAdd(&g_cnt[d0.z], 1); atomicAdd(&g_cnt[d0.w], 1);
        atomicAdd(&g_cnt[d1.x], 1); atomicAdd(&g_cnt[d1.y], 1);
        atomicAdd(&g_cnt[d1.z], 1); atomicAdd(&g_cnt[d1.w], 1);
    } else {
        int j = n8 * 8 + (i - n8);
        if (j < e) atomicAdd(&g_cnt[dst[j]], 1);
    }
}

// Single-kernel exclusive scan with decoupled lookback.
// Writes rowptr, cursor, dinv. 49 blocks — all co-resident, progress safe.
__global__ __launch_bounds__(SCAN_BS) void k_scan(int n) {
    __shared__ int s[SCAN_BS];
    __shared__ int s_excl;
    const int b = blockIdx.x;
    const int t = threadIdx.x;
    const int i = b * SCAN_BS + t;

    int c = (i < n) ? g_cnt[i] : 0;
    s[t] = c;
    __syncthreads();
    // Hillis–Steele inclusive scan
    for (int off = 1; off < SCAN_BS; off <<= 1) {
        int v = (t >= off) ? s[t - off] : 0;
        __syncthreads();
        s[t] += v;
        __syncthreads();
    }
    int incl = s[t];
    int total = s[SCAN_BS - 1];

    if (t == 0) {
        if (b == 0) {
            g_pref[0] = total;
            __threadfence();
            g_flag[0] = 2;
            s_excl = 0;
        } else {
            g_aggr[b] = total;
            __threadfence();
            g_flag[b] = 1;
            // lookback
            int excl = 0;
            for (int j = b - 1; j >= 0; j--) {
                int f;
                do { f = g_flag[j]; } while (f == 0);
                __threadfence();
                if (f == 2) { excl += g_pref[j]; break; }
                excl += g_aggr[j];
            }
            g_pref[b] = excl + total;
            __threadfence();
            g_flag[b] = 2;
            s_excl = excl;
        }
    }
    __syncthreads();
    int ex = s_excl + incl - c;

    if (i < n) {
        g_rowptr[i] = ex;
        g_cursor[i] = ex;
        g_dinv[i]   = rsqrtf((float)(c + 1));
        if (i == n - 1) g_rowptr[n] = ex + c;
    }
}

// fill edge records {src, dinv[src]} bucketed by dst
__global__ void k_fill(const int* __restrict__ src, const int* __restrict__ dst, int e) {
    int i = blockIdx.x * blockDim.x + threadIdx.x;
    int n4 = e >> 2;
    if (i < n4) {
        int4 s = __ldg(reinterpret_cast<const int4*>(src) + i);
        int4 d = __ldg(reinterpret_cast<const int4*>(dst) + i);
        float v0 = g_dinv[s.x], v1 = g_dinv[s.y], v2 = g_dinv[s.z], v3 = g_dinv[s.w];
        int p0 = atomicAdd(&g_cursor[d.x], 1);
        int p1 = atomicAdd(&g_cursor[d.y], 1);
        int p2 = atomicAdd(&g_cursor[d.z], 1);
        int p3 = atomicAdd(&g_cursor[d.w], 1);
        g_erec[p0] = make_int2(s.x, __float_as_int(v0));
        g_erec[p1] = make_int2(s.y, __float_as_int(v1));
        g_erec[p2] = make_int2(s.z, __float_as_int(v2));
        g_erec[p3] = make_int2(s.w, __float_as_int(v3));
    } else {
        int j = n4 * 4 + (i - n4);
        if (j < e) {
            int s = src[j];
            int p = atomicAdd(&g_cursor[dst[j]], 1);
            g_erec[p] = make_int2(s, __float_as_int(g_dinv[s]));
        }
    }
}

// ---------------------------------------------------------------------------
// 3xTF32 mma.sync GEMM: Yh[row] = fp16( (relu?)X[row] @ W )
// Block: 64 rows x 128 cols, K=128 full. 256 threads (8 warps, 2x4 warp grid).
// ---------------------------------------------------------------------------
#define LDA 132
#define LDB 136
#define SM_A (64 * LDA)
#define SM_B (128 * LDB)
#define SM_GEMM_BYTES ((2 * SM_A + 2 * SM_B) * 4)

__device__ __forceinline__ void mma_tf32(float* c, const uint32_t* a, const uint32_t* b) {
    asm volatile(
        "mma.sync.aligned.m16n8k8.row.col.f32.tf32.tf32.f32 "
        "{%0,%1,%2,%3}, {%4,%5,%6,%7}, {%8,%9}, {%0,%1,%2,%3};"
        : "+f"(c[0]), "+f"(c[1]), "+f"(c[2]), "+f"(c[3])
        : "r"(a[0]), "r"(a[1]), "r"(a[2]), "r"(a[3]), "r"(b[0]), "r"(b[1]));
}

template <bool RELU>
__global__ __launch_bounds__(256) void k_gemm_mma(const float* __restrict__ X,
                                                  const float* __restrict__ W,
                                                  __half* __restrict__ Y, int n) {
    extern __shared__ uint32_t sm[];
    uint32_t* sAh = sm;
    uint32_t* sAl = sAh + SM_A;
    uint32_t* sBh = sAl + SM_A;
    uint32_t* sBl = sBh + SM_B;

    const int tid  = threadIdx.x;
    const int row0 = blockIdx.x * 64;

#pragma unroll
    for (int idx = tid; idx < 64 * 32; idx += 256) {
        int r  = idx >> 5;
        int c4 = idx & 31;
        int row = row0 + r;
        float4 v = make_float4(0.f, 0.f, 0.f, 0.f);
        if (row < n) v = __ldg(reinterpret_cast<const float4*>(X + (size_t)row * DD) + c4);
        if (RELU) {
            v.x = fmaxf(v.x, 0.f); v.y = fmaxf(v.y, 0.f);
            v.z = fmaxf(v.z, 0.f); v.w = fmaxf(v.w, 0.f);
        }
        uint4 h, l;
        h.x = f2tf(v.x); l.x = f2tf(v.x - __uint_as_float(h.x));
        h.y = f2tf(v.y); l.y = f2tf(v.y - __uint_as_float(h.y));
        h.z = f2tf(v.z); l.z = f2tf(v.z - __uint_as_float(h.z));
        h.w = f2tf(v.w); l.w = f2tf(v.w - __uint_as_float(h.w));
        *reinterpret_cast<uint4*>(&sAh[r * LDA + c4 * 4]) = h;
        *reinterpret_cast<uint4*>(&sAl[r * LDA + c4 * 4]) = l;
    }

#pragma unroll
    for (int idx = tid; idx < 128 * 32; idx += 256) {
        int k  = idx >> 5;
        int c4 = idx & 31;
        float4 v = __ldg(reinterpret_cast<const float4*>(W + (size_t)k * DD) + c4);
        uint4 h, l;
        h.x = f2tf(v.x); l.x = f2tf(v.x - __uint_as_float(h.x));
        h.y = f2tf(v.y); l.y = f2tf(v.y - __uint_as_float(h.y));
        h.z = f2tf(v.z); l.z = f2tf(v.z - __uint_as_float(h.z));
        h.w = f2tf(v.w); l.w = f2tf(v.w - __uint_as_float(h.w));
        *reinterpret_cast<uint4*>(&sBh[k * LDB + c4 * 4]) = h;
        *reinterpret_cast<uint4*>(&sBl[k * LDB + c4 * 4]) = l;
    }
    __syncthreads();

    const int wid  = tid >> 5;
    const int lane = tid & 31;
    const int gid  = lane >> 2;
    const int tig  = lane & 3;
    const int wm   = wid & 1;
    const int wn   = wid >> 1;

    float acc[2][4][4];
#pragma unroll
    for (int mi = 0; mi < 2; mi++)
#pragma unroll
        for (int ni = 0; ni < 4; ni++)
#pragma unroll
            for (int j = 0; j < 4; j++) acc[mi][ni][j] = 0.f;

    for (int p = 0; p < 3; p++) {
        const uint32_t* As = (p == 2) ? sAl : sAh;
        const uint32_t* Bs = (p == 1) ? sBl : sBh;
#pragma unroll
        for (int ks = 0; ks < 16; ks++) {
            const int k0 = ks * 8;
            uint32_t a[2][4];
#pragma unroll
            for (int mi = 0; mi < 2; mi++) {
                int rb = wm * 32 + mi * 16;
                a[mi][0] = As[(rb + gid) * LDA + k0 + tig];
                a[mi][1] = As[(rb + gid + 8) * LDA + k0 + tig];
                a[mi][2] = As[(rb + gid) * LDA + k0 + tig + 4];
                a[mi][3] = As[(rb + gid + 8) * LDA + k0 + tig + 4];
            }
            uint32_t b[4][2];
#pragma unroll
            for (int ni = 0; ni < 4; ni++) {
                int nb = wn * 32 + ni * 8;
                b[ni][0] = Bs[(k0 + tig) * LDB + nb + gid];
                b[ni][1] = Bs[(k0 + tig + 4) * LDB + nb + gid];
            }
#pragma unroll
            for (int mi = 0; mi < 2; mi++)
#pragma unroll
                for (int ni = 0; ni < 4; ni++)
                    mma_tf32(acc[mi][ni], a[mi], b[ni]);
        }
    }

    // ---- Epilogue: convert to fp16 (half2 stores) ----
#pragma unroll
    for (int mi = 0; mi < 2; mi++) {
        int r0 = row0 + wm * 32 + mi * 16 + gid;
#pragma unroll
        for (int ni = 0; ni < 4; ni++) {
            int col = wn * 32 + ni * 8 + tig * 2;
            if (r0 < n)
                *reinterpret_cast<__half2*>(Y + (size_t)r0 * DD + col) =
                    __float22half2_rn(make_float2(acc[mi][ni][0], acc[mi][ni][1]));
            if (r0 + 8 < n)
                *reinterpret_cast<__half2*>(Y + (size_t)(r0 + 8) * DD + col) =
                    __float22half2_rn(make_float2(acc[mi][ni][2], acc[mi][ni][3]));
        }
    }
}

// ---------------------------------------------------------------------------
// Gather (fp16 input, fp32 accumulate/output):
// out[i] = dinv[i] * (dinv[i]*h[i] + sum_in dinv[s]*h[s]) + b
// One warp per node; lane owns 4 cols (8B of halves). Unroll 8.
// ---------------------------------------------------------------------------
__global__ __launch_bounds__(256) void k_gather(const __half* __restrict__ hs,
                                                const float* __restrict__ b,
                                                float* __restrict__ out, int n) {
    int g    = blockIdx.x * blockDim.x + threadIdx.x;
    int node = g >> 5;
    int lane = g & 31;
    if (node >= n) return;

    const uint2* H = reinterpret_cast<const uint2*>(hs);  // 32 uint2 per row
    int beg = g_rowptr[node];
    int end = g_rowptr[node + 1];

    float dn = g_dinv[node];
    uint2 sraw = __ldg(&H[(size_t)node * 32 + lane]);
    float2 slo = __half22float2(*reinterpret_cast<__half2*>(&sraw.x));
    float2 shi = __half22float2(*reinterpret_cast<__half2*>(&sraw.y));
    float4 acc = make_float4(slo.x * dn, slo.y * dn, shi.x * dn, shi.y * dn);

    int e = beg;
    for (; e + 8 <= end; e += 8) {
        int2 r[8];
#pragma unroll
        for (int j = 0; j < 8; j++) r[j] = __ldg(&g_erec[e + j]);
        uint2 v[8];
#pragma unroll
        for (int j = 0; j < 8; j++) v[j] = __ldg(&H[(size_t)r[j].x * 32 + lane]);
#pragma unroll
        for (int j = 0; j < 8; j++) {
            float d = __int_as_float(r[j].y);
            float2 lo = __half22float2(*reinterpret_cast<__half2*>(&v[j].x));
            float2 hi = __half22float2(*reinterpret_cast<__half2*>(&v[j].y));
            acc.x = fmaf(lo.x, d, acc.x);
            acc.y = fmaf(lo.y, d, acc.y);
            acc.z = fmaf(hi.x, d, acc.z);
            acc.w = fmaf(hi.y, d, acc.w);
        }
    }
    for (; e < end; e++) {
        int2 r = __ldg(&g_erec[e]);
        float d = __int_as_float(r.y);
        uint2 v = __ldg(&H[(size_t)r.x * 32 + lane]);
        float2 lo = __half22float2(*reinterpret_cast<__half2*>(&v.x));
        float2 hi = __half22float2(*reinterpret_cast<__half2*>(&v.y));
        acc.x = fmaf(lo.x, d, acc.x);
        acc.y = fmaf(lo.y, d, acc.y);
        acc.z = fmaf(hi.x, d, acc.z);
        acc.w = fmaf(hi.y, d, acc.w);
    }

    float4 bb = __ldg(reinterpret_cast<const float4*>(b) + lane);
    float4 o;
    o.x = fmaf(acc.x, dn, bb.x);
    o.y = fmaf(acc.y, dn, bb.y);
    o.z = fmaf(acc.z, dn, bb.z);
    o.w = fmaf(acc.w, dn, bb.w);
    reinterpret_cast<float4*>(out)[(size_t)node * 32 + lane] = o;
}

// ---------------------------------------------------------------------------
// Stream/event resources
// ---------------------------------------------------------------------------
static cudaStream_t g_s1 = nullptr;
static cudaEvent_t  g_evf = nullptr, g_evj = nullptr;
namespace {
struct StreamInit {
    StreamInit() {
        if (cudaStreamCreateWithFlags(&g_s1, cudaStreamNonBlocking) != cudaSuccess) g_s1 = nullptr;
        if (cudaEventCreateWithFlags(&g_evf, cudaEventDisableTiming) != cudaSuccess) g_evf = nullptr;
        if (cudaEventCreateWithFlags(&g_evj, cudaEventDisableTiming) != cudaSuccess) g_evj = nullptr;
        cudaGetLastError();
    }
} g_stream_init;
}

// ---------------------------------------------------------------------------
// Launch
// ---------------------------------------------------------------------------
extern "C" void kernel_launch(void* const* d_in, const int* in_sizes, int n_in,
                              void* d_out, int out_size) {
    const float* x  = (const float*)d_in[0];
    const int*   ei = (const int*)d_in[1];
    const float* W1 = (const float*)d_in[2];
    const float* b1 = (const float*)d_in[3];
    const float* W2 = (const float*)d_in[4];
    const float* b2 = (const float*)d_in[5];
    float* out = (float*)d_out;

    const int n = in_sizes[0] / DD;   // 50000
    const int e = in_sizes[1] / 2;    // 800000
    const int* src = ei;
    const int* dst = ei + e;

    __half* p_h = nullptr; float* p_a = nullptr;
    cudaGetSymbolAddress((void**)&p_h, g_h);
    cudaGetSymbolAddress((void**)&p_a, g_a);

    cudaFuncSetAttribute(k_gemm_mma<false>, cudaFuncAttributeMaxDynamicSharedMemorySize, SM_GEMM_BYTES);
    cudaFuncSetAttribute(k_gemm_mma<true>,  cudaFuncAttributeMaxDynamicSharedMemorySize, SM_GEMM_BYTES);

    const int T = 256;
    const int nb = (n + SCAN_BS - 1) / SCAN_BS;   // 49
    const int e8threads = (e >> 3) + 8;
    const int e4threads = (e >> 2) + 4;
    const int gemm_blocks = (n + 63) / 64;
    const long long nwt = (long long)n * 32;
    const int gath_blocks = (int)((nwt + T - 1) / T);

    const bool fork = (g_s1 && g_evf && g_evj);
    cudaStream_t sc = fork ? g_s1 : (cudaStream_t)0;

    if (fork) {
        cudaEventRecord(g_evf, 0);
        cudaStreamWaitEvent(g_s1, g_evf, 0);
    }

    // CSR + normalization (side stream, overlapped with GEMM-1)
    k_zero <<<(n + T - 1) / T, T, 0, sc>>>(n);
    k_hist <<<(e8threads + T - 1) / T, T, 0, sc>>>(dst, e);
    k_scan <<<nb, SCAN_BS, 0, sc>>>(n);
    k_fill <<<(e4threads + T - 1) / T, T, 0, sc>>>(src, dst, e);

    // GEMM-1 on main stream (independent of CSR)
    k_gemm_mma<false><<<gemm_blocks, 256, SM_GEMM_BYTES>>>(x, W1, p_h, n);

    if (fork) {
        cudaEventRecord(g_evj, g_s1);
        cudaStreamWaitEvent(0, g_evj, 0);
    }

    // Layer 1 aggregate, Layer 2
    k_gather<<<gath_blocks, T>>>(p_h, b1, p_a, n);
    k_gemm_mma<true><<<gemm_blocks, 256, SM_GEMM_BYTES>>>(p_a, W2, p_h, n);
    k_gather<<<gath_blocks, T>>>(p_h, b2, out, n);
}

// round 9
// speedup vs baseline: 1.2398x; 1.1987x over previous
#include <cuda_runtime.h>
#include <cuda_fp16.h>
#include <cuda_bf16.h>
#include <cstdint>

#define NN 50000
#define DD 128
#define EE 800000
#define SCAN_BS 1024
#define NB_MAX 64

// ---------------------------------------------------------------------------
// Scratch (__device__ globals; no allocations allowed)
// ---------------------------------------------------------------------------
__device__ int   g_cnt[NN];
__device__ int   g_rowptr[NN + 1];
__device__ int   g_cursor[NN];
__device__ int2  g_erec[EE];               // {src, bitcast(dinv[src])}
__device__ float g_dinv[NN];
__device__ __half g_h[(size_t)NN * DD];    // GEMM output in fp16 (gather input)
__device__ float  g_a[(size_t)NN * DD];    // layer-1 output (fp32)

// pre-split weights: bf16x2 pairs along k. Wp[kk][n] = {W[2kk][n], W[2kk+1][n]}
__device__ uint32_t g_wh[2][64 * 128];
__device__ uint32_t g_wl[2][64 * 128];

// decoupled-lookback scan state (reset by k_zero each call)
__device__ volatile int g_flag[NB_MAX];
__device__ int g_aggr[NB_MAX];
__device__ int g_pref[NB_MAX];

// ---------------------------------------------------------------------------
// CSR build
// ---------------------------------------------------------------------------
__global__ void k_zero(int n) {
    int i = blockIdx.x * blockDim.x + threadIdx.x;
    if (i < n) g_cnt[i] = 0;
    if (i < NB_MAX) g_flag[i] = 0;
}

__global__ void k_hist(const int* __restrict__ dst, int e) {
    int i = blockIdx.x * blockDim.x + threadIdx.x;
    int n8 = e >> 3;
    if (i < n8) {
        int4 d0 = __ldg(reinterpret_cast<const int4*>(dst) + 2 * i);
        int4 d1 = __ldg(reinterpret_cast<const int4*>(dst) + 2 * i + 1);
        atomicAdd(&g_cnt[d0.x], 1); atomicAdd(&g_cnt[d0.y], 1);
        atomicAdd(&g_cnt[d0.z], 1); atomicAdd(&g_cnt[d0.w], 1);
        atomicAdd(&g_cnt[d1.x], 1); atomicAdd(&g_cnt[d1.y], 1);
        atomicAdd(&g_cnt[d1.z], 1); atomicAdd(&g_cnt[d1.w], 1);
    } else {
        int j = n8 * 8 + (i - n8);
        if (j < e) atomicAdd(&g_cnt[dst[j]], 1);
    }
}

// Single-kernel exclusive scan with decoupled lookback (49 blocks co-resident).
__global__ __launch_bounds__(SCAN_BS) void k_scan(int n) {
    __shared__ int s[SCAN_BS];
    __shared__ int s_excl;
    const int b = blockIdx.x;
    const int t = threadIdx.x;
    const int i = b * SCAN_BS + t;

    int c = (i < n) ? g_cnt[i] : 0;
    s[t] = c;
    __syncthreads();
    for (int off = 1; off < SCAN_BS; off <<= 1) {
        int v = (t >= off) ? s[t - off] : 0;
        __syncthreads();
        s[t] += v;
        __syncthreads();
    }
    int incl = s[t];
    int total = s[SCAN_BS - 1];

    if (t == 0) {
        if (b == 0) {
            g_pref[0] = total;
            __threadfence();
            g_flag[0] = 2;
            s_excl = 0;
        } else {
            g_aggr[b] = total;
            __threadfence();
            g_flag[b] = 1;
            int excl = 0;
            for (int j = b - 1; j >= 0; j--) {
                int f;
                do { f = g_flag[j]; } while (f == 0);
                __threadfence();
                if (f == 2) { excl += g_pref[j]; break; }
                excl += g_aggr[j];
            }
            g_pref[b] = excl + total;
            __threadfence();
            g_flag[b] = 2;
            s_excl = excl;
        }
    }
    __syncthreads();
    int ex = s_excl + incl - c;

    if (i < n) {
        g_rowptr[i] = ex;
        g_cursor[i] = ex;
        g_dinv[i]   = rsqrtf((float)(c + 1));
        if (i == n - 1) g_rowptr[n] = ex + c;
    }
}

// fill edge records {src, dinv[src]} bucketed by dst — 8 edges per thread
__global__ void k_fill(const int* __restrict__ src, const int* __restrict__ dst, int e) {
    int i = blockIdx.x * blockDim.x + threadIdx.x;
    int n8 = e >> 3;
    if (i < n8) {
        int4 s0 = __ldg(reinterpret_cast<const int4*>(src) + 2 * i);
        int4 s1 = __ldg(reinterpret_cast<const int4*>(src) + 2 * i + 1);
        int4 d0 = __ldg(reinterpret_cast<const int4*>(dst) + 2 * i);
        int4 d1 = __ldg(reinterpret_cast<const int4*>(dst) + 2 * i + 1);
        int ss[8] = {s0.x, s0.y, s0.z, s0.w, s1.x, s1.y, s1.z, s1.w};
        int dd[8] = {d0.x, d0.y, d0.z, d0.w, d1.x, d1.y, d1.z, d1.w};
        float dv[8];
#pragma unroll
        for (int j = 0; j < 8; j++) dv[j] = g_dinv[ss[j]];
        int pp[8];
#pragma unroll
        for (int j = 0; j < 8; j++) pp[j] = atomicAdd(&g_cursor[dd[j]], 1);
#pragma unroll
        for (int j = 0; j < 8; j++) g_erec[pp[j]] = make_int2(ss[j], __float_as_int(dv[j]));
    } else {
        int j = n8 * 8 + (i - n8);
        if (j < e) {
            int s = src[j];
            int p = atomicAdd(&g_cursor[dst[j]], 1);
            g_erec[p] = make_int2(s, __float_as_int(g_dinv[s]));
        }
    }
}

// ---------------------------------------------------------------------------
// Weight split: Wp[kk][n] bf16x2 {W[2kk][n], W[2kk+1][n]}, hi + lo planes.
// ---------------------------------------------------------------------------
__global__ void k_wsplit(const float* __restrict__ W, int which) {
    int i = blockIdx.x * blockDim.x + threadIdx.x;
    if (i >= 64 * 128) return;
    int kk = i >> 7, nn = i & 127;
    float w0 = __ldg(&W[(2 * kk) * 128 + nn]);
    float w1 = __ldg(&W[(2 * kk + 1) * 128 + nn]);
    __nv_bfloat16 h0 = __float2bfloat16(w0);
    __nv_bfloat16 h1 = __float2bfloat16(w1);
    __nv_bfloat16 l0 = __float2bfloat16(w0 - __bfloat162float(h0));
    __nv_bfloat16 l1 = __float2bfloat16(w1 - __bfloat162float(h1));
    __nv_bfloat162 hh = __nv_bfloat162(h0, h1);
    __nv_bfloat162 ll = __nv_bfloat162(l0, l1);
    g_wh[which][i] = *reinterpret_cast<uint32_t*>(&hh);
    g_wl[which][i] = *reinterpret_cast<uint32_t*>(&ll);
}

// ---------------------------------------------------------------------------
// 3x-bf16 mma.sync GEMM: Yh[row] = fp16( (relu?)X[row] @ W )
// Block: 64 rows x 128 cols, K=128. 256 threads (2x4 warp grid, 32x32 warp tile).
// D = Ah*Bh + Ah*Bl + Al*Bh. A (hi/lo bf16x2) in smem, B direct from L1.
// ---------------------------------------------------------------------------
#define LDAB 68   // u32 stride per row (64 pairs + pad)

__device__ __forceinline__ void mma_bf16(float* c, const uint32_t* a, const uint32_t* b) {
    asm volatile(
        "mma.sync.aligned.m16n8k16.row.col.f32.bf16.bf16.f32 "
        "{%0,%1,%2,%3}, {%4,%5,%6,%7}, {%8,%9}, {%0,%1,%2,%3};"
        : "+f"(c[0]), "+f"(c[1]), "+f"(c[2]), "+f"(c[3])
        : "r"(a[0]), "r"(a[1]), "r"(a[2]), "r"(a[3]), "r"(b[0]), "r"(b[1]));
}

template <bool RELU>
__global__ __launch_bounds__(256) void k_gemm_mma(const float* __restrict__ X,
                                                  const float* __restrict__ Wh,
                                                  const float* __restrict__ Wl_unused,
                                                  int widx,
                                                  __half* __restrict__ Y, int n) {
    __shared__ uint32_t sAh[64 * LDAB];
    __shared__ uint32_t sAl[64 * LDAB];

    const int tid  = threadIdx.x;
    const int row0 = blockIdx.x * 64;
    const uint32_t* __restrict__ Bh = g_wh[widx];
    const uint32_t* __restrict__ Bl = g_wl[widx];

    // ---- A tile load + bf16 hi/lo split (pairs along k) ----
#pragma unroll
    for (int idx = tid; idx < 64 * 32; idx += 256) {
        int r  = idx >> 5;
        int c4 = idx & 31;
        int row = row0 + r;
        float4 v = make_float4(0.f, 0.f, 0.f, 0.f);
        if (row < n) v = __ldg(reinterpret_cast<const float4*>(X + (size_t)row * DD) + c4);
        if (RELU) {
            v.x = fmaxf(v.x, 0.f); v.y = fmaxf(v.y, 0.f);
            v.z = fmaxf(v.z, 0.f); v.w = fmaxf(v.w, 0.f);
        }
        __nv_bfloat16 hx = __float2bfloat16(v.x), hy = __float2bfloat16(v.y);
        __nv_bfloat16 hz = __float2bfloat16(v.z), hw = __float2bfloat16(v.w);
        __nv_bfloat16 lx = __float2bfloat16(v.x - __bfloat162float(hx));
        __nv_bfloat16 ly = __float2bfloat16(v.y - __bfloat162float(hy));
        __nv_bfloat16 lz = __float2bfloat16(v.z - __bfloat162float(hz));
        __nv_bfloat16 lw = __float2bfloat16(v.w - __bfloat162float(hw));
        __nv_bfloat162 h0 = __nv_bfloat162(hx, hy), h1 = __nv_bfloat162(hz, hw);
        __nv_bfloat162 l0 = __nv_bfloat162(lx, ly), l1 = __nv_bfloat162(lz, lw);
        uint2 hp = make_uint2(*reinterpret_cast<uint32_t*>(&h0), *reinterpret_cast<uint32_t*>(&h1));
        uint2 lp = make_uint2(*reinterpret_cast<uint32_t*>(&l0), *reinterpret_cast<uint32_t*>(&l1));
        *reinterpret_cast<uint2*>(&sAh[r * LDAB + 2 * c4]) = hp;
        *reinterpret_cast<uint2*>(&sAl[r * LDAB + 2 * c4]) = lp;
    }
    __syncthreads();

    const int wid  = tid >> 5;
    const int lane = tid & 31;
    const int gid  = lane >> 2;
    const int tig  = lane & 3;
    const int wm   = wid & 1;     // 2 warps along M (32 rows)
    const int wn   = wid >> 1;    // 4 warps along N (32 cols)

    float acc[2][4][4];
#pragma unroll
    for (int mi = 0; mi < 2; mi++)
#pragma unroll
        for (int ni = 0; ni < 4; ni++)
#pragma unroll
            for (int j = 0; j < 4; j++) acc[mi][ni][j] = 0.f;

#pragma unroll
    for (int ks = 0; ks < 8; ks++) {
        const int kk0 = ks * 8;   // pair index base (k0 = ks*16)
        uint32_t ah[2][4], al[2][4];
#pragma unroll
        for (int mi = 0; mi < 2; mi++) {
            int rb = wm * 32 + mi * 16;
            ah[mi][0] = sAh[(rb + gid) * LDAB + kk0 + tig];
            ah[mi][1] = sAh[(rb + gid + 8) * LDAB + kk0 + tig];
            ah[mi][2] = sAh[(rb + gid) * LDAB + kk0 + 4 + tig];
            ah[mi][3] = sAh[(rb + gid + 8) * LDAB + kk0 + 4 + tig];
            al[mi][0] = sAl[(rb + gid) * LDAB + kk0 + tig];
            al[mi][1] = sAl[(rb + gid + 8) * LDAB + kk0 + tig];
            al[mi][2] = sAl[(rb + gid) * LDAB + kk0 + 4 + tig];
            al[mi][3] = sAl[(rb + gid + 8) * LDAB + kk0 + 4 + tig];
        }
        uint32_t bh[4][2], bl[4][2];
#pragma unroll
        for (int ni = 0; ni < 4; ni++) {
            int nb = wn * 32 + ni * 8 + gid;
            bh[ni][0] = __ldg(&Bh[(kk0 + tig) * 128 + nb]);
            bh[ni][1] = __ldg(&Bh[(kk0 + 4 + tig) * 128 + nb]);
            bl[ni][0] = __ldg(&Bl[(kk0 + tig) * 128 + nb]);
            bl[ni][1] = __ldg(&Bl[(kk0 + 4 + tig) * 128 + nb]);
        }
#pragma unroll
        for (int mi = 0; mi < 2; mi++)
#pragma unroll
            for (int ni = 0; ni < 4; ni++) {
                mma_bf16(acc[mi][ni], ah[mi], bh[ni]);
                mma_bf16(acc[mi][ni], ah[mi], bl[ni]);
                mma_bf16(acc[mi][ni], al[mi], bh[ni]);
            }
    }

    // ---- Epilogue: fp16 half2 stores ----
#pragma unroll
    for (int mi = 0; mi < 2; mi++) {
        int r0 = row0 + wm * 32 + mi * 16 + gid;
#pragma unroll
        for (int ni = 0; ni < 4; ni++) {
            int col = wn * 32 + ni * 8 + tig * 2;
            if (r0 < n)
                *reinterpret_cast<__half2*>(Y + (size_t)r0 * DD + col) =
                    __float22half2_rn(make_float2(acc[mi][ni][0], acc[mi][ni][1]));
            if (r0 + 8 < n)
                *reinterpret_cast<__half2*>(Y + (size_t)(r0 + 8) * DD + col) =
                    __float22half2_rn(make_float2(acc[mi][ni][2], acc[mi][ni][3]));
        }
    }
}

// ---------------------------------------------------------------------------
// Gather (fp16 input, fp32 accumulate): 16 lanes per node, 2 nodes per warp.
// out[i] = dinv[i] * (dinv[i]*h[i] + sum_in dinv[s]*h[s]) + b
// ---------------------------------------------------------------------------
__global__ __launch_bounds__(256) void k_gather(const __half* __restrict__ hs,
                                                const float* __restrict__ bias,
                                                float* __restrict__ out, int n) {
    int g    = blockIdx.x * blockDim.x + threadIdx.x;
    int node = g >> 4;
    int lane = g & 15;
    if (node >= n) return;

    const uint4* H = reinterpret_cast<const uint4*>(hs);  // 16 uint4 per row
    int beg = g_rowptr[node];
    int end = g_rowptr[node + 1];

    float dn = g_dinv[node];
    float acc[8];
    {
        uint4 sraw = __ldg(&H[(size_t)node * 16 + lane]);
        const __half2* ph = reinterpret_cast<const __half2*>(&sraw);
#pragma unroll
        for (int q = 0; q < 4; q++) {
            float2 f = __half22float2(ph[q]);
            acc[2 * q]     = f.x * dn;
            acc[2 * q + 1] = f.y * dn;
        }
    }

    int e = beg;
    for (; e + 8 <= end; e += 8) {
        int2 r[8];
#pragma unroll
        for (int j = 0; j < 8; j++) r[j] = __ldg(&g_erec[e + j]);
        uint4 v[8];
#pragma unroll
        for (int j = 0; j < 8; j++) v[j] = __ldg(&H[(size_t)r[j].x * 16 + lane]);
#pragma unroll
        for (int j = 0; j < 8; j++) {
            float d = __int_as_float(r[j].y);
            const __half2* pv = reinterpret_cast<const __half2*>(&v[j]);
#pragma unroll
            for (int q = 0; q < 4; q++) {
                float2 f = __half22float2(pv[q]);
                acc[2 * q]     = fmaf(f.x, d, acc[2 * q]);
                acc[2 * q + 1] = fmaf(f.y, d, acc[2 * q + 1]);
            }
        }
    }
    for (; e < end; e++) {
        int2 r = __ldg(&g_erec[e]);
        float d = __int_as_float(r.y);
        uint4 v = __ldg(&H[(size_t)r.x * 16 + lane]);
        const __half2* pv = reinterpret_cast<const __half2*>(&v);
#pragma unroll
        for (int q = 0; q < 4; q++) {
            float2 f = __half22float2(pv[q]);
            acc[2 * q]     = fmaf(f.x, d, acc[2 * q]);
            acc[2 * q + 1] = fmaf(f.y, d, acc[2 * q + 1]);
        }
    }

    const float4* B4 = reinterpret_cast<const float4*>(bias);
    float4 b0 = __ldg(&B4[lane * 2]);
    float4 b1 = __ldg(&B4[lane * 2 + 1]);
    float4 o0, o1;
    o0.x = fmaf(acc[0], dn, b0.x); o0.y = fmaf(acc[1], dn, b0.y);
    o0.z = fmaf(acc[2], dn, b0.z); o0.w = fmaf(acc[3], dn, b0.w);
    o1.x = fmaf(acc[4], dn, b1.x); o1.y = fmaf(acc[5], dn, b1.y);
    o1.z = fmaf(acc[6], dn, b1.z); o1.w = fmaf(acc[7], dn, b1.w);
    float4* O = reinterpret_cast<float4*>(out);
    O[(size_t)node * 32 + lane * 2]     = o0;
    O[(size_t)node * 32 + lane * 2 + 1] = o1;
}

// ---------------------------------------------------------------------------
// Stream/event resources
// ---------------------------------------------------------------------------
static cudaStream_t g_s1 = nullptr;
static cudaEvent_t  g_evf = nullptr, g_evj = nullptr;
namespace {
struct StreamInit {
    StreamInit() {
        if (cudaStreamCreateWithFlags(&g_s1, cudaStreamNonBlocking) != cudaSuccess) g_s1 = nullptr;
        if (cudaEventCreateWithFlags(&g_evf, cudaEventDisableTiming) != cudaSuccess) g_evf = nullptr;
        if (cudaEventCreateWithFlags(&g_evj, cudaEventDisableTiming) != cudaSuccess) g_evj = nullptr;
        cudaGetLastError();
    }
} g_stream_init;
}

// ---------------------------------------------------------------------------
// Launch
// ---------------------------------------------------------------------------
extern "C" void kernel_launch(void* const* d_in, const int* in_sizes, int n_in,
                              void* d_out, int out_size) {
    const float* x  = (const float*)d_in[0];
    const int*   ei = (const int*)d_in[1];
    const float* W1 = (const float*)d_in[2];
    const float* b1 = (const float*)d_in[3];
    const float* W2 = (const float*)d_in[4];
    const float* b2 = (const float*)d_in[5];
    float* out = (float*)d_out;

    const int n = in_sizes[0] / DD;   // 50000
    const int e = in_sizes[1] / 2;    // 800000
    const int* src = ei;
    const int* dst = ei + e;

    __half* p_h = nullptr; float* p_a = nullptr;
    cudaGetSymbolAddress((void**)&p_h, g_h);
    cudaGetSymbolAddress((void**)&p_a, g_a);

    const int T = 256;
    const int nb = (n + SCAN_BS - 1) / SCAN_BS;   // 49
    const int e8threads = (e >> 3) + 8;
    const int gemm_blocks = (n + 63) / 64;
    const long long ngt = (long long)n * 16;
    const int gath_blocks = (int)((ngt + T - 1) / T);

    const bool fork = (g_s1 && g_evf && g_evj);
    cudaStream_t sc = fork ? g_s1 : (cudaStream_t)0;

    if (fork) {
        cudaEventRecord(g_evf, 0);
        cudaStreamWaitEvent(g_s1, g_evf, 0);
    }

    // CSR + normalization (side stream, overlapped with W-split + GEMM-1)
    k_zero <<<(n + T - 1) / T, T, 0, sc>>>(n);
    k_hist <<<(e8threads + T - 1) / T, T, 0, sc>>>(dst, e);
    k_scan <<<nb, SCAN_BS, 0, sc>>>(n);
    k_fill <<<(e8threads + T - 1) / T, T, 0, sc>>>(src, dst, e);

    // Main stream: weight splits + GEMM-1 (independent of CSR)
    k_wsplit<<<(64 * 128 + T - 1) / T, T>>>(W1, 0);
    k_wsplit<<<(64 * 128 + T - 1) / T, T>>>(W2, 1);
    k_gemm_mma<false><<<gemm_blocks, 256>>>(x, nullptr, nullptr, 0, p_h, n);

    if (fork) {
        cudaEventRecord(g_evj, g_s1);
        cudaStreamWaitEvent(0, g_evj, 0);
    }

    // Layer 1 aggregate, Layer 2
    k_gather<<<gath_blocks, T>>>(p_h, b1, p_a, n);
    k_gemm_mma<true><<<gemm_blocks, 256>>>(p_a, nullptr, nullptr, 1, p_h, n);
    k_gather<<<gath_blocks, T>>>(p_h, b2, out, n);
}

// round 10
// speedup vs baseline: 1.3454x; 1.0851x over previous
#include <cuda_runtime.h>
#include <cuda_fp16.h>
#include <cuda_bf16.h>
#include <cstdint>

#define NN 50000
#define DD 128
#define EE 800000
#define SCAN_BS 1024
#define NB_MAX 64

// ---------------------------------------------------------------------------
// Scratch (__device__ globals; no allocations allowed)
// ---------------------------------------------------------------------------
__device__ int   g_cnt[NN];
__device__ int   g_rowptr[NN + 1];
__device__ int   g_rank[EE];               // per-edge rank within dst bucket
__device__ int   g_col[EE];                // CSR column (src ids), by dst
__device__ float g_dinv[NN];
__device__ __half g_h[(size_t)NN * DD];    // hs = dinv[row] * (X@W)  (fp16)
__device__ float  g_a[(size_t)NN * DD];    // layer-1 output (fp32)

// pre-split weights: bf16x2 pairs along k. Wp[kk][n] = {W[2kk][n], W[2kk+1][n]}
__device__ uint32_t g_wh[2][64 * 128];
__device__ uint32_t g_wl[2][64 * 128];

// decoupled-lookback scan state (reset by k_zero each call)
__device__ volatile int g_flag[NB_MAX];
__device__ int g_aggr[NB_MAX];
__device__ int g_pref[NB_MAX];

// ---------------------------------------------------------------------------
// CSR build
// ---------------------------------------------------------------------------
__global__ void k_zero(int n) {
    int i = blockIdx.x * blockDim.x + threadIdx.x;
    if (i < n) g_cnt[i] = 0;
    if (i < NB_MAX) g_flag[i] = 0;
}

// histogram + per-edge rank capture
__global__ void k_hist(const int* __restrict__ dst, int e) {
    int i = blockIdx.x * blockDim.x + threadIdx.x;
    int n8 = e >> 3;
    if (i < n8) {
        int4 d0 = __ldg(reinterpret_cast<const int4*>(dst) + 2 * i);
        int4 d1 = __ldg(reinterpret_cast<const int4*>(dst) + 2 * i + 1);
        int dd[8] = {d0.x, d0.y, d0.z, d0.w, d1.x, d1.y, d1.z, d1.w};
        int rr[8];
#pragma unroll
        for (int j = 0; j < 8; j++) rr[j] = atomicAdd(&g_cnt[dd[j]], 1);
        int4 r0 = make_int4(rr[0], rr[1], rr[2], rr[3]);
        int4 r1 = make_int4(rr[4], rr[5], rr[6], rr[7]);
        reinterpret_cast<int4*>(g_rank)[2 * i]     = r0;
        reinterpret_cast<int4*>(g_rank)[2 * i + 1] = r1;
    } else {
        int j = n8 * 8 + (i - n8);
        if (j < e) g_rank[j] = atomicAdd(&g_cnt[dst[j]], 1);
    }
}

// Single-kernel exclusive scan with decoupled lookback (49 blocks co-resident).
__global__ __launch_bounds__(SCAN_BS) void k_scan(int n) {
    __shared__ int s[SCAN_BS];
    __shared__ int s_excl;
    const int b = blockIdx.x;
    const int t = threadIdx.x;
    const int i = b * SCAN_BS + t;

    int c = (i < n) ? g_cnt[i] : 0;
    s[t] = c;
    __syncthreads();
    for (int off = 1; off < SCAN_BS; off <<= 1) {
        int v = (t >= off) ? s[t - off] : 0;
        __syncthreads();
        s[t] += v;
        __syncthreads();
    }
    int incl = s[t];
    int total = s[SCAN_BS - 1];

    if (t == 0) {
        if (b == 0) {
            g_pref[0] = total;
            __threadfence();
            g_flag[0] = 2;
            s_excl = 0;
        } else {
            g_aggr[b] = total;
            __threadfence();
            g_flag[b] = 1;
            int excl = 0;
            for (int j = b - 1; j >= 0; j--) {
                int f;
                do { f = g_flag[j]; } while (f == 0);
                __threadfence();
                if (f == 2) { excl += g_pref[j]; break; }
                excl += g_aggr[j];
            }
            g_pref[b] = excl + total;
            __threadfence();
            g_flag[b] = 2;
            s_excl = excl;
        }
    }
    __syncthreads();
    int ex = s_excl + incl - c;

    if (i < n) {
        g_rowptr[i] = ex;
        g_dinv[i]   = rsqrtf((float)(c + 1));
        if (i == n - 1) g_rowptr[n] = ex + c;
    }
}

// atomic-free fill: pos = rowptr[dst] + rank
__global__ void k_fill(const int* __restrict__ src, const int* __restrict__ dst, int e) {
    int i = blockIdx.x * blockDim.x + threadIdx.x;
    int n8 = e >> 3;
    if (i < n8) {
        int4 s0 = __ldg(reinterpret_cast<const int4*>(src) + 2 * i);
        int4 s1 = __ldg(reinterpret_cast<const int4*>(src) + 2 * i + 1);
        int4 d0 = __ldg(reinterpret_cast<const int4*>(dst) + 2 * i);
        int4 d1 = __ldg(reinterpret_cast<const int4*>(dst) + 2 * i + 1);
        int4 r0 = __ldg(reinterpret_cast<const int4*>(g_rank) + 2 * i);
        int4 r1 = __ldg(reinterpret_cast<const int4*>(g_rank) + 2 * i + 1);
        int ss[8] = {s0.x, s0.y, s0.z, s0.w, s1.x, s1.y, s1.z, s1.w};
        int dd[8] = {d0.x, d0.y, d0.z, d0.w, d1.x, d1.y, d1.z, d1.w};
        int rr[8] = {r0.x, r0.y, r0.z, r0.w, r1.x, r1.y, r1.z, r1.w};
        int pp[8];
#pragma unroll
        for (int j = 0; j < 8; j++) pp[j] = __ldg(&g_rowptr[dd[j]]) + rr[j];
#pragma unroll
        for (int j = 0; j < 8; j++) g_col[pp[j]] = ss[j];
    } else {
        int j = n8 * 8 + (i - n8);
        if (j < e) g_col[__ldg(&g_rowptr[dst[j]]) + g_rank[j]] = src[j];
    }
}

// ---------------------------------------------------------------------------
// Weight split: Wp[kk][n] bf16x2 {W[2kk][n], W[2kk+1][n]}, hi + lo planes.
// ---------------------------------------------------------------------------
__global__ void k_wsplit(const float* __restrict__ W, int which) {
    int i = blockIdx.x * blockDim.x + threadIdx.x;
    if (i >= 64 * 128) return;
    int kk = i >> 7, nn = i & 127;
    float w0 = __ldg(&W[(2 * kk) * 128 + nn]);
    float w1 = __ldg(&W[(2 * kk + 1) * 128 + nn]);
    __nv_bfloat16 h0 = __float2bfloat16(w0);
    __nv_bfloat16 h1 = __float2bfloat16(w1);
    __nv_bfloat16 l0 = __float2bfloat16(w0 - __bfloat162float(h0));
    __nv_bfloat16 l1 = __float2bfloat16(w1 - __bfloat162float(h1));
    __nv_bfloat162 hh = __nv_bfloat162(h0, h1);
    __nv_bfloat162 ll = __nv_bfloat162(l0, l1);
    g_wh[which][i] = *reinterpret_cast<uint32_t*>(&hh);
    g_wl[which][i] = *reinterpret_cast<uint32_t*>(&ll);
}

// ---------------------------------------------------------------------------
// 3x-bf16 mma.sync GEMM: Yh[row] = fp16( dinv[row] * ((relu?)X[row] @ W) )
// Block: 64 rows x 128 cols, K=128. 256 threads (2x4 warp grid, 32x32 warp tile).
// ---------------------------------------------------------------------------
#define LDAB 68   // u32 stride per row (64 pairs + pad)

__device__ __forceinline__ void mma_bf16(float* c, const uint32_t* a, const uint32_t* b) {
    asm volatile(
        "mma.sync.aligned.m16n8k16.row.col.f32.bf16.bf16.f32 "
        "{%0,%1,%2,%3}, {%4,%5,%6,%7}, {%8,%9}, {%0,%1,%2,%3};"
        : "+f"(c[0]), "+f"(c[1]), "+f"(c[2]), "+f"(c[3])
        : "r"(a[0]), "r"(a[1]), "r"(a[2]), "r"(a[3]), "r"(b[0]), "r"(b[1]));
}

template <bool RELU>
__global__ __launch_bounds__(256) void k_gemm_mma(const float* __restrict__ X,
                                                  int widx,
                                                  __half* __restrict__ Y, int n) {
    __shared__ uint32_t sAh[64 * LDAB];
    __shared__ uint32_t sAl[64 * LDAB];

    const int tid  = threadIdx.x;
    const int row0 = blockIdx.x * 64;
    const uint32_t* __restrict__ Bh = g_wh[widx];
    const uint32_t* __restrict__ Bl = g_wl[widx];

    // ---- A tile load + bf16 hi/lo split (pairs along k) ----
#pragma unroll
    for (int idx = tid; idx < 64 * 32; idx += 256) {
        int r  = idx >> 5;
        int c4 = idx & 31;
        int row = row0 + r;
        float4 v = make_float4(0.f, 0.f, 0.f, 0.f);
        if (row < n) v = __ldg(reinterpret_cast<const float4*>(X + (size_t)row * DD) + c4);
        if (RELU) {
            v.x = fmaxf(v.x, 0.f); v.y = fmaxf(v.y, 0.f);
            v.z = fmaxf(v.z, 0.f); v.w = fmaxf(v.w, 0.f);
        }
        __nv_bfloat16 hx = __float2bfloat16(v.x), hy = __float2bfloat16(v.y);
        __nv_bfloat16 hz = __float2bfloat16(v.z), hw = __float2bfloat16(v.w);
        __nv_bfloat16 lx = __float2bfloat16(v.x - __bfloat162float(hx));
        __nv_bfloat16 ly = __float2bfloat16(v.y - __bfloat162float(hy));
        __nv_bfloat16 lz = __float2bfloat16(v.z - __bfloat162float(hz));
        __nv_bfloat16 lw = __float2bfloat16(v.w - __bfloat162float(hw));
        __nv_bfloat162 h0 = __nv_bfloat162(hx, hy), h1 = __nv_bfloat162(hz, hw);
        __nv_bfloat162 l0 = __nv_bfloat162(lx, ly), l1 = __nv_bfloat162(lz, lw);
        uint2 hp = make_uint2(*reinterpret_cast<uint32_t*>(&h0), *reinterpret_cast<uint32_t*>(&h1));
        uint2 lp = make_uint2(*reinterpret_cast<uint32_t*>(&l0), *reinterpret_cast<uint32_t*>(&l1));
        *reinterpret_cast<uint2*>(&sAh[r * LDAB + 2 * c4]) = hp;
        *reinterpret_cast<uint2*>(&sAl[r * LDAB + 2 * c4]) = lp;
    }
    __syncthreads();

    const int wid  = tid >> 5;
    const int lane = tid & 31;
    const int gid  = lane >> 2;
    const int tig  = lane & 3;
    const int wm   = wid & 1;
    const int wn   = wid >> 1;

    float acc[2][4][4];
#pragma unroll
    for (int mi = 0; mi < 2; mi++)
#pragma unroll
        for (int ni = 0; ni < 4; ni++)
#pragma unroll
            for (int j = 0; j < 4; j++) acc[mi][ni][j] = 0.f;

#pragma unroll
    for (int ks = 0; ks < 8; ks++) {
        const int kk0 = ks * 8;
        uint32_t ah[2][4], al[2][4];
#pragma unroll
        for (int mi = 0; mi < 2; mi++) {
            int rb = wm * 32 + mi * 16;
            ah[mi][0] = sAh[(rb + gid) * LDAB + kk0 + tig];
            ah[mi][1] = sAh[(rb + gid + 8) * LDAB + kk0 + tig];
            ah[mi][2] = sAh[(rb + gid) * LDAB + kk0 + 4 + tig];
            ah[mi][3] = sAh[(rb + gid + 8) * LDAB + kk0 + 4 + tig];
            al[mi][0] = sAl[(rb + gid) * LDAB + kk0 + tig];
            al[mi][1] = sAl[(rb + gid + 8) * LDAB + kk0 + tig];
            al[mi][2] = sAl[(rb + gid) * LDAB + kk0 + 4 + tig];
            al[mi][3] = sAl[(rb + gid + 8) * LDAB + kk0 + 4 + tig];
        }
        uint32_t bh[4][2], bl[4][2];
#pragma unroll
        for (int ni = 0; ni < 4; ni++) {
            int nb = wn * 32 + ni * 8 + gid;
            bh[ni][0] = __ldg(&Bh[(kk0 + tig) * 128 + nb]);
            bh[ni][1] = __ldg(&Bh[(kk0 + 4 + tig) * 128 + nb]);
            bl[ni][0] = __ldg(&Bl[(kk0 + tig) * 128 + nb]);
            bl[ni][1] = __ldg(&Bl[(kk0 + 4 + tig) * 128 + nb]);
        }
#pragma unroll
        for (int mi = 0; mi < 2; mi++)
#pragma unroll
            for (int ni = 0; ni < 4; ni++) {
                mma_bf16(acc[mi][ni], ah[mi], bh[ni]);
                mma_bf16(acc[mi][ni], ah[mi], bl[ni]);
                mma_bf16(acc[mi][ni], al[mi], bh[ni]);
            }
    }

    // ---- Epilogue: scale by dinv[row], convert to fp16 ----
#pragma unroll
    for (int mi = 0; mi < 2; mi++) {
        int r0 = row0 + wm * 32 + mi * 16 + gid;
        float dA = (r0 < n)     ? g_dinv[r0]     : 0.f;
        float dB = (r0 + 8 < n) ? g_dinv[r0 + 8] : 0.f;
#pragma unroll
        for (int ni = 0; ni < 4; ni++) {
            int col = wn * 32 + ni * 8 + tig * 2;
            if (r0 < n)
                *reinterpret_cast<__half2*>(Y + (size_t)r0 * DD + col) =
                    __float22half2_rn(make_float2(acc[mi][ni][0] * dA, acc[mi][ni][1] * dA));
            if (r0 + 8 < n)
                *reinterpret_cast<__half2*>(Y + (size_t)(r0 + 8) * DD + col) =
                    __float22half2_rn(make_float2(acc[mi][ni][2] * dB, acc[mi][ni][3] * dB));
        }
    }
}

// ---------------------------------------------------------------------------
// Gather: out[i] = dinv[i] * (hs[i] + sum_in hs[src]) + b
// 16 lanes per node, 2 nodes per warp, unroll 8. hs carries dinv[src] already.
// ---------------------------------------------------------------------------
__global__ __launch_bounds__(256) void k_gather(const __half* __restrict__ hs,
                                                const float* __restrict__ bias,
                                                float* __restrict__ out, int n) {
    int g    = blockIdx.x * blockDim.x + threadIdx.x;
    int node = g >> 4;
    int lane = g & 15;
    if (node >= n) return;

    const uint4* H = reinterpret_cast<const uint4*>(hs);  // 16 uint4 per row
    int beg = g_rowptr[node];
    int end = g_rowptr[node + 1];

    float acc[8];
    {
        uint4 sraw = __ldg(&H[(size_t)node * 16 + lane]);
        const __half2* ph = reinterpret_cast<const __half2*>(&sraw);
#pragma unroll
        for (int q = 0; q < 4; q++) {
            float2 f = __half22float2(ph[q]);
            acc[2 * q]     = f.x;
            acc[2 * q + 1] = f.y;
        }
    }

    int e = beg;
    for (; e + 8 <= end; e += 8) {
        int c[8];
#pragma unroll
        for (int j = 0; j < 8; j++) c[j] = __ldg(&g_col[e + j]);
        uint4 v[8];
#pragma unroll
        for (int j = 0; j < 8; j++) v[j] = __ldg(&H[(size_t)c[j] * 16 + lane]);
#pragma unroll
        for (int j = 0; j < 8; j++) {
            const __half2* pv = reinterpret_cast<const __half2*>(&v[j]);
#pragma unroll
            for (int q = 0; q < 4; q++) {
                float2 f = __half22float2(pv[q]);
                acc[2 * q]     += f.x;
                acc[2 * q + 1] += f.y;
            }
        }
    }
    for (; e < end; e++) {
        uint4 v = __ldg(&H[(size_t)__ldg(&g_col[e]) * 16 + lane]);
        const __half2* pv = reinterpret_cast<const __half2*>(&v);
#pragma unroll
        for (int q = 0; q < 4; q++) {
            float2 f = __half22float2(pv[q]);
            acc[2 * q]     += f.x;
            acc[2 * q + 1] += f.y;
        }
    }

    float dn = g_dinv[node];
    const float4* B4 = reinterpret_cast<const float4*>(bias);
    float4 b0 = __ldg(&B4[lane * 2]);
    float4 b1 = __ldg(&B4[lane * 2 + 1]);
    float4 o0, o1;
    o0.x = fmaf(acc[0], dn, b0.x); o0.y = fmaf(acc[1], dn, b0.y);
    o0.z = fmaf(acc[2], dn, b0.z); o0.w = fmaf(acc[3], dn, b0.w);
    o1.x = fmaf(acc[4], dn, b1.x); o1.y = fmaf(acc[5], dn, b1.y);
    o1.z = fmaf(acc[6], dn, b1.z); o1.w = fmaf(acc[7], dn, b1.w);
    float4* O = reinterpret_cast<float4*>(out);
    O[(size_t)node * 32 + lane * 2]     = o0;
    O[(size_t)node * 32 + lane * 2 + 1] = o1;
}

// ---------------------------------------------------------------------------
// Stream/event resources
// ---------------------------------------------------------------------------
static cudaStream_t g_s1 = nullptr;
static cudaEvent_t  g_evf = nullptr, g_evs = nullptr, g_evj = nullptr;
namespace {
struct StreamInit {
    StreamInit() {
        if (cudaStreamCreateWithFlags(&g_s1, cudaStreamNonBlocking) != cudaSuccess) g_s1 = nullptr;
        if (cudaEventCreateWithFlags(&g_evf, cudaEventDisableTiming) != cudaSuccess) g_evf = nullptr;
        if (cudaEventCreateWithFlags(&g_evs, cudaEventDisableTiming) != cudaSuccess) g_evs = nullptr;
        if (cudaEventCreateWithFlags(&g_evj, cudaEventDisableTiming) != cudaSuccess) g_evj = nullptr;
        cudaGetLastError();
    }
} g_stream_init;
}

// ---------------------------------------------------------------------------
// Launch
// ---------------------------------------------------------------------------
extern "C" void kernel_launch(void* const* d_in, const int* in_sizes, int n_in,
                              void* d_out, int out_size) {
    const float* x  = (const float*)d_in[0];
    const int*   ei = (const int*)d_in[1];
    const float* W1 = (const float*)d_in[2];
    const float* b1 = (const float*)d_in[3];
    const float* W2 = (const float*)d_in[4];
    const float* b2 = (const float*)d_in[5];
    float* out = (float*)d_out;

    const int n = in_sizes[0] / DD;   // 50000
    const int e = in_sizes[1] / 2;    // 800000
    const int* src = ei;
    const int* dst = ei + e;

    __half* p_h = nullptr; float* p_a = nullptr;
    cudaGetSymbolAddress((void**)&p_h, g_h);
    cudaGetSymbolAddress((void**)&p_a, g_a);

    const int T = 256;
    const int nb = (n + SCAN_BS - 1) / SCAN_BS;   // 49
    const int e8threads = (e >> 3) + 8;
    const int gemm_blocks = (n + 63) / 64;
    const long long ngt = (long long)n * 16;
    const int gath_blocks = (int)((ngt + T - 1) / T);

    const bool fork = (g_s1 && g_evf && g_evs && g_evj);
    cudaStream_t sc = fork ? g_s1 : (cudaStream_t)0;

    if (fork) {
        cudaEventRecord(g_evf, 0);
        cudaStreamWaitEvent(g_s1, g_evf, 0);
    }

    // Side stream: CSR chain. scan completion signaled early (GEMM-1 needs dinv).
    k_zero <<<(n + T - 1) / T, T, 0, sc>>>(n);
    k_hist <<<(e8threads + T - 1) / T, T, 0, sc>>>(dst, e);
    k_scan <<<nb, SCAN_BS, 0, sc>>>(n);
    if (fork) cudaEventRecord(g_evs, sc);
    k_fill <<<(e8threads + T - 1) / T, T, 0, sc>>>(src, dst, e);
    if (fork) cudaEventRecord(g_evj, sc);

    // Main stream: weight splits (independent), then GEMM-1 (needs dinv).
    k_wsplit<<<(64 * 128 + T - 1) / T, T>>>(W1, 0);
    k_wsplit<<<(64 * 128 + T - 1) / T, T>>>(W2, 1);
    if (fork) cudaStreamWaitEvent(0, g_evs, 0);
    k_gemm_mma<false><<<gemm_blocks, 256>>>(x, 0, p_h, n);
    if (fork) cudaStreamWaitEvent(0, g_evj, 0);

    // Layer 1 aggregate, Layer 2
    k_gather<<<gath_blocks, T>>>(p_h, b1, p_a, n);
    k_gemm_mma<true><<<gemm_blocks, 256>>>(p_a, 1, p_h, n);
    k_gather<<<gath_blocks, T>>>(p_h, b2, out, n);
}